// round 6
// baseline (speedup 1.0000x reference)
#include <cuda_runtime.h>

typedef unsigned long long u64;

#define NB      16384
#define ADIM    32
#define KTOT    2048
#define EDIM    128
#define NACT    1000
#define ODIM    64

// Scratch (no runtime allocation allowed -> __device__ globals)
__device__ float g_s_table[NACT];
__device__ float g_T2[NACT * ODIM];
__device__ float g_emb[NB * EDIM];

__device__ __forceinline__ u64 fma2(u64 a, u64 b, u64 c) {
    u64 d;
    asm("fma.rn.f32x2 %0, %1, %2, %3;" : "=l"(d) : "l"(a), "l"(b), "l"(c));
    return d;
}
__device__ __forceinline__ float2 unpack2(u64 v) {
    float2 f;
    asm("mov.b64 {%0, %1}, %2;" : "=f"(f.x), "=f"(f.y) : "l"(v));
    return f;
}

// ---------------------------------------------------------------------------
// Kernel 0: s_table[n] = action_table[n]·W_att + b_att
//           T2[n][o]   = action_table[n]·W_out[128: , o]
// grid = 1000 blocks x 64 threads
// ---------------------------------------------------------------------------
__global__ void prep_kernel(const float* __restrict__ table,
                            const float* __restrict__ W_att,
                            const float* __restrict__ b_att,
                            const float* __restrict__ W_out)
{
    __shared__ float row[EDIM];
    __shared__ float red[64];
    const int n = blockIdx.x;
    const int t = threadIdx.x;   // 0..63
    row[t]      = table[n * EDIM + t];
    row[t + 64] = table[n * EDIM + t + 64];
    __syncthreads();

    red[t] = row[t] * W_att[t] + row[t + 64] * W_att[t + 64];
    __syncthreads();
    #pragma unroll
    for (int s = 32; s > 0; s >>= 1) {
        if (t < s) red[t] += red[t + s];
        __syncthreads();
    }
    if (t == 0) g_s_table[n] = red[0] + b_att[0];

    float acc = 0.f;
    #pragma unroll 8
    for (int e = 0; e < EDIM; e++)
        acc = fmaf(row[e], W_out[(EDIM + e) * ODIM + t], acc);
    g_T2[n * ODIM + t] = acc;
}

// ---------------------------------------------------------------------------
// Kernel 1: g_emb = state_flat @ W_state + b_state   (16384x2048 @ 2048x128)
// BM=64, BN=128(full E), BK=16, 256 threads, thread tile 4x8.
// A tile stored DUPLICATED in smem ((a,a) pairs) so inner loop is pure
// LDS + fma.rn.f32x2 (2 FMAs/inst) -> ~2x fp32 throughput.
// Register double-buffered global->smem pipeline.
// ---------------------------------------------------------------------------
#define BM 64
#define BK 16
#define AST 132                 // duplicated-A row stride (floats), padded
#define NTILE (KTOT / BK)       // 128

__global__ void __launch_bounds__(256, 2) gemm_kernel(
    const float* __restrict__ state,
    const float* __restrict__ Wst,
    const float* __restrict__ b_state)
{
    __shared__ float As[2][BK * AST];    // As[k][2m],[2m+1] both = A[k][m]
    __shared__ float Bs[2][BK * EDIM];

    const int tid = threadIdx.x;
    const int rowBase = blockIdx.x * BM;

    // A loads: 64x16 tile, one float4 per thread
    const int aRow = tid >> 2;                 // 0..63
    const int aK4  = (tid & 3) << 2;           // 0,4,8,12
    const float* aPtr = state + (size_t)(rowBase + aRow) * KTOT + aK4;

    // B loads: 16x128 tile, two float4 per thread
    const int bRow = tid >> 5;                 // 0..7 (and +8)
    const int bCol = (tid & 31) << 2;          // 0..124

    // compute mapping: 16x16 thread grid, 4 rows x 8 cols each
    const int tc = (tid & 15) << 3;            // col base
    const int tr = (tid >> 4) << 2;            // row base

    float4 aReg  = *(const float4*)aPtr;
    float4 bReg0 = *(const float4*)(Wst + (size_t)bRow * EDIM + bCol);
    float4 bReg1 = *(const float4*)(Wst + (size_t)(bRow + 8) * EDIM + bCol);

    {
        float av[4] = {aReg.x, aReg.y, aReg.z, aReg.w};
        #pragma unroll
        for (int j = 0; j < 4; j++)
            *(float2*)&As[0][(aK4 + j) * AST + 2 * aRow] = make_float2(av[j], av[j]);
        *(float4*)&Bs[0][bRow * EDIM + bCol]       = bReg0;
        *(float4*)&Bs[0][(bRow + 8) * EDIM + bCol] = bReg1;
    }
    __syncthreads();

    u64 acc[4][4] = {};   // packed fp32 pairs: rows i, col pairs (tc+2j, tc+2j+1)

    int buf = 0;
    for (int t = 0; t < NTILE; t++) {
        if (t + 1 < NTILE) {
            const int k0 = (t + 1) * BK;
            aReg  = *(const float4*)(aPtr + k0);
            bReg0 = *(const float4*)(Wst + (size_t)(k0 + bRow) * EDIM + bCol);
            bReg1 = *(const float4*)(Wst + (size_t)(k0 + bRow + 8) * EDIM + bCol);
        }
        const float* Asb = As[buf];
        const float* Bsb = Bs[buf];
        #pragma unroll
        for (int k = 0; k < BK; k++) {
            u64 pa[4];
            #pragma unroll
            for (int i = 0; i < 4; i++)
                pa[i] = *(const u64*)&Asb[k * AST + 2 * (tr + i)];
            ulonglong2 bb0 = *(const ulonglong2*)&Bsb[k * EDIM + tc];
            ulonglong2 bb1 = *(const ulonglong2*)&Bsb[k * EDIM + tc + 4];
            #pragma unroll
            for (int i = 0; i < 4; i++) {
                acc[i][0] = fma2(pa[i], bb0.x, acc[i][0]);
                acc[i][1] = fma2(pa[i], bb0.y, acc[i][1]);
                acc[i][2] = fma2(pa[i], bb1.x, acc[i][2]);
                acc[i][3] = fma2(pa[i], bb1.y, acc[i][3]);
            }
        }
        if (t + 1 < NTILE) {
            const int nb = buf ^ 1;
            float av[4] = {aReg.x, aReg.y, aReg.z, aReg.w};
            #pragma unroll
            for (int j = 0; j < 4; j++)
                *(float2*)&As[nb][(aK4 + j) * AST + 2 * aRow] = make_float2(av[j], av[j]);
            *(float4*)&Bs[nb][bRow * EDIM + bCol]       = bReg0;
            *(float4*)&Bs[nb][(bRow + 8) * EDIM + bCol] = bReg1;
        }
        __syncthreads();
        buf ^= 1;
    }

    const float4 bs0 = *(const float4*)&b_state[tc];
    const float4 bs1 = *(const float4*)&b_state[tc + 4];
    #pragma unroll
    for (int i = 0; i < 4; i++) {
        const size_t row = rowBase + tr + i;
        float2 v0 = unpack2(acc[i][0]);
        float2 v1 = unpack2(acc[i][1]);
        float2 v2 = unpack2(acc[i][2]);
        float2 v3 = unpack2(acc[i][3]);
        float4 o0 = make_float4(v0.x + bs0.x, v0.y + bs0.y, v1.x + bs0.z, v1.y + bs0.w);
        float4 o1 = make_float4(v2.x + bs1.x, v2.y + bs1.y, v3.x + bs1.z, v3.y + bs1.w);
        *(float4*)&g_emb[row * EDIM + tc]     = o0;
        *(float4*)&g_emb[row * EDIM + tc + 4] = o1;
    }
}

// ---------------------------------------------------------------------------
// Kernel 2: per row b:
//   w = softmax(s_table[action[b,:]])
//   out[b,:] = g_emb[b,:] @ W_out[0:128,:] + sum_a w_a * T2[act_a,:] + b_out
// One warp per 4 rows; 8 warps/block -> 32 rows/block, 512 blocks.
// W_out[0:128] cached in smem; lane handles output pair (2*lane, 2*lane+1).
// ---------------------------------------------------------------------------
__global__ void __launch_bounds__(256) epilogue_kernel(
    const int* __restrict__ action,
    const float* __restrict__ W_out,
    const float* __restrict__ b_out,
    float* __restrict__ out)
{
    __shared__ float Ws1[EDIM * ODIM];   // 32 KB: W_out rows 0..127 (8192 floats)
    __shared__ float xs[8][4][EDIM];     // 16 KB: per-warp emb rows

    const int tid = threadIdx.x;
    // FIX (R5 bug): load ALL 8192 floats of W_out[0:128,:], not just 2048.
    // 256 threads x 8 float4 = 8192 floats.
    #pragma unroll
    for (int i = 0; i < 8; i++) {
        const int idx4 = tid + i * 256;             // float4 index 0..2047
        *(float4*)&Ws1[idx4 * 4] = *(const float4*)&W_out[idx4 * 4];
    }
    __syncthreads();

    const int w = tid >> 5;
    const int lane = tid & 31;
    const int base = blockIdx.x * 32 + w * 4;

    int acts[4];
    float wgt[4];
    #pragma unroll
    for (int i = 0; i < 4; i++) {
        acts[i] = action[(base + i) * ADIM + lane];
        float s = g_s_table[acts[i]];
        float m = s;
        #pragma unroll
        for (int o = 16; o > 0; o >>= 1)
            m = fmaxf(m, __shfl_xor_sync(0xffffffffu, m, o));
        float p = __expf(s - m);
        float sum = p;
        #pragma unroll
        for (int o = 16; o > 0; o >>= 1)
            sum += __shfl_xor_sync(0xffffffffu, sum, o);
        wgt[i] = p / sum;
    }

    // attention contribution via precomputed T2
    float att0[4] = {0.f, 0.f, 0.f, 0.f};
    float att1[4] = {0.f, 0.f, 0.f, 0.f};
    for (int a = 0; a < 32; a++) {
        #pragma unroll
        for (int i = 0; i < 4; i++) {
            int id   = __shfl_sync(0xffffffffu, acts[i], a);
            float wa = __shfl_sync(0xffffffffu, wgt[i], a);
            float2 t2 = *(const float2*)&g_T2[id * ODIM + 2 * lane];
            att0[i] = fmaf(wa, t2.x, att0[i]);
            att1[i] = fmaf(wa, t2.y, att1[i]);
        }
    }

    // emb rows -> smem for all-lane broadcast
    #pragma unroll
    for (int i = 0; i < 4; i++) {
        float4 v = *(const float4*)&g_emb[(size_t)(base + i) * EDIM + lane * 4];
        *(float4*)&xs[w][i][lane * 4] = v;
    }
    __syncwarp();

    float acc0[4] = {0.f, 0.f, 0.f, 0.f};
    float acc1[4] = {0.f, 0.f, 0.f, 0.f};
    #pragma unroll 4
    for (int e = 0; e < EDIM; e++) {
        float2 wv = *(const float2*)&Ws1[e * ODIM + 2 * lane];
        #pragma unroll
        for (int i = 0; i < 4; i++) {
            float x = xs[w][i][e];
            acc0[i] = fmaf(x, wv.x, acc0[i]);
            acc1[i] = fmaf(x, wv.y, acc1[i]);
        }
    }

    const float2 bo = *(const float2*)&b_out[2 * lane];
    #pragma unroll
    for (int i = 0; i < 4; i++) {
        float2 r;
        r.x = acc0[i] + att0[i] + bo.x;
        r.y = acc1[i] + att1[i] + bo.y;
        *(float2*)&out[(size_t)(base + i) * ODIM + 2 * lane] = r;
    }
}

// ---------------------------------------------------------------------------
extern "C" void kernel_launch(void* const* d_in, const int* in_sizes, int n_in,
                              void* d_out, int out_size)
{
    const float* state   = (const float*)d_in[0];
    const int*   action  = (const int*)  d_in[1];
    const float* W_state = (const float*)d_in[2];
    const float* b_state = (const float*)d_in[3];
    const float* table   = (const float*)d_in[4];
    const float* W_att   = (const float*)d_in[5];
    const float* b_att   = (const float*)d_in[6];
    const float* W_out   = (const float*)d_in[7];
    const float* b_out   = (const float*)d_in[8];
    float* out = (float*)d_out;

    prep_kernel<<<NACT, 64>>>(table, W_att, b_att, W_out);
    gemm_kernel<<<NB / BM, 256>>>(state, W_state, b_state);
    epilogue_kernel<<<NB / 32, 256>>>(action, W_out, b_out, out);
}

// round 10
// speedup vs baseline: 2.8306x; 2.8306x over previous
#include <cuda_runtime.h>
#include <cuda_bf16.h>
#include <cstdint>

#define NB      16384
#define ADIM    32
#define KTOT    2048
#define EDIM    128
#define NACT    1000
#define ODIM    64

#define KC      32                 // K per chunk (bf16 elems)
#define NCHUNK  (KTOT / KC)        // 64
#define PITCH   40                 // bf16 per smem row (80 bytes) -> conflict-free ldmatrix
#define TILE_B  (128 * PITCH * 2)  // 10240 bytes per tile
#define BUF_B   (4 * TILE_B)       // Ah Al Bh Bl = 40960
#define DSMEM   (2 * BUF_B)        // 81920 (double buffer)

// ---------------- scratch ----------------
__device__ float g_s_table[NACT];
__device__ float g_T2[NACT * ODIM];
__device__ float g_emb[NB * EDIM];
__device__ __nv_bfloat16 g_Wt_h[EDIM * KTOT];   // W^T hi, [E][K]
__device__ __nv_bfloat16 g_Wt_l[EDIM * KTOT];   // W^T lo

// ---------------- helpers ----------------
__device__ __forceinline__ uint32_t smem_u32(const void* p) {
    uint32_t a;
    asm("{ .reg .u64 t; cvta.to.shared.u64 t, %1; cvt.u32.u64 %0, t; }"
        : "=r"(a) : "l"(p));
    return a;
}
__device__ __forceinline__ void ldsm_x4(uint32_t* r, uint32_t addr) {
    asm volatile("ldmatrix.sync.aligned.m8n8.x4.shared.b16 {%0,%1,%2,%3}, [%4];"
                 : "=r"(r[0]), "=r"(r[1]), "=r"(r[2]), "=r"(r[3]) : "r"(addr));
}
__device__ __forceinline__ void mma_bf16(float* c, const uint32_t* a, const uint32_t* b) {
    asm volatile(
        "mma.sync.aligned.m16n8k16.row.col.f32.bf16.bf16.f32 "
        "{%0,%1,%2,%3}, {%4,%5,%6,%7}, {%8,%9}, {%0,%1,%2,%3};"
        : "+f"(c[0]), "+f"(c[1]), "+f"(c[2]), "+f"(c[3])
        : "r"(a[0]), "r"(a[1]), "r"(a[2]), "r"(a[3]), "r"(b[0]), "r"(b[1]));
}
__device__ __forceinline__ void split2(float x, float y, uint32_t& hi, uint32_t& lo) {
    __nv_bfloat162 h = __floats2bfloat162_rn(x, y);
    __nv_bfloat162 l = __floats2bfloat162_rn(x - __low2float(h), y - __high2float(h));
    hi = *reinterpret_cast<uint32_t*>(&h);
    lo = *reinterpret_cast<uint32_t*>(&l);
}

// ---------------------------------------------------------------------------
// prep_w: W_state [K,E] f32 -> g_Wt_h/g_Wt_l [E][K] bf16 (transposed split)
// ---------------------------------------------------------------------------
__global__ void prep_w_kernel(const float* __restrict__ W)
{
    const int idx = blockIdx.x * 256 + threadIdx.x;   // 0..65535
    const int e  = idx >> 9;                          // 0..127
    const int k4 = (idx & 511) << 2;                  // 0..2044
    float v[4];
    #pragma unroll
    for (int j = 0; j < 4; j++)
        v[j] = __ldg(&W[(size_t)(k4 + j) * EDIM + e]);
    uint2 hh, ll;
    split2(v[0], v[1], hh.x, ll.x);
    split2(v[2], v[3], hh.y, ll.y);
    *(uint2*)&g_Wt_h[(size_t)e * KTOT + k4] = hh;
    *(uint2*)&g_Wt_l[(size_t)e * KTOT + k4] = ll;
}

// ---------------------------------------------------------------------------
// prep2: s_table + T2, smem-cached W_out2. grid 63 x 256.
// ---------------------------------------------------------------------------
__global__ void __launch_bounds__(256) prep2_kernel(
    const float* __restrict__ table, const float* __restrict__ W_att,
    const float* __restrict__ b_att, const float* __restrict__ W_out)
{
    __shared__ float Wo2[EDIM * ODIM];
    __shared__ float rows[16][EDIM];
    __shared__ float watt[EDIM];

    const int tid = threadIdx.x;
    #pragma unroll
    for (int i = 0; i < 32; i++)
        Wo2[tid + i * 256] = W_out[EDIM * ODIM + tid + i * 256];
    if (tid < EDIM) watt[tid] = W_att[tid];

    const int r0 = blockIdx.x * 16;
    for (int idx = tid; idx < 16 * EDIM; idx += 256) {
        const int r = idx >> 7, e = idx & 127;
        rows[r][e] = (r0 + r < NACT) ? table[(size_t)(r0 + r) * EDIM + e] : 0.f;
    }
    __syncthreads();

    if (tid < 16 && r0 + tid < NACT) {
        float s = 0.f;
        #pragma unroll 8
        for (int e = 0; e < EDIM; e++) s = fmaf(rows[tid][e], watt[e], s);
        g_s_table[r0 + tid] = s + b_att[0];
    }

    #pragma unroll
    for (int i = 0; i < 4; i++) {
        const int idx = tid + i * 256;
        const int r = idx >> 6, o = idx & 63;
        if (r0 + r < NACT) {
            float acc = 0.f;
            #pragma unroll 8
            for (int e = 0; e < EDIM; e++)
                acc = fmaf(rows[r][e], Wo2[e * ODIM + o], acc);
            g_T2[(size_t)(r0 + r) * ODIM + o] = acc;
        }
    }
}

// ---------------------------------------------------------------------------
// gemm_mma: g_emb = state @ W_state + b_state, bf16 3-split via mma.sync.
// CTA 128x128, 8 warps (4m x 2n), K chunks of 32, double-buffered smem.
// ---------------------------------------------------------------------------
__global__ void __launch_bounds__(256)
gemm_mma_kernel(const float* __restrict__ state, const float* __restrict__ b_state)
{
    extern __shared__ __align__(128) char dsm[];
    const uint32_t dyn = smem_u32(dsm);

    const int tid = threadIdx.x;
    const int wid = tid >> 5, lane = tid & 31;
    const int warp_m = wid & 3;          // 0..3 -> 32 rows each
    const int warp_n = wid >> 2;         // 0..1 -> 64 cols each
    const int rowBase = blockIdx.x * 128;

    // fill mapping: 2 threads per row
    const int frow = tid >> 1;           // 0..127
    const int fseg = (tid & 1) * 16;     // 0 or 16 (k offset)
    const float* asrc = state + (size_t)(rowBase + frow) * KTOT + fseg;
    const __nv_bfloat16* bh_src = g_Wt_h + (size_t)frow * KTOT + fseg;
    const __nv_bfloat16* bl_src = g_Wt_l + (size_t)frow * KTOT + fseg;
    const uint32_t fAoff = frow * (PITCH * 2) + fseg * 2;   // byte offset in tile

    // ldmatrix lane addressing pieces
    const int lg = lane >> 3, lr = lane & 7;

    float acc[2][8][4];
    #pragma unroll
    for (int mi = 0; mi < 2; mi++)
        #pragma unroll
        for (int j = 0; j < 8; j++)
            #pragma unroll
            for (int q = 0; q < 4; q++) acc[mi][j][q] = 0.f;

    // ---- prologue: fill buffer 0 (chunk 0) ----
    {
        char* base = dsm;
        #pragma unroll
        for (int i = 0; i < 4; i++) {
            float4 v = __ldg((const float4*)(asrc + i * 4));
            uint2 hh, ll;
            split2(v.x, v.y, hh.x, ll.x);
            split2(v.z, v.w, hh.y, ll.y);
            *(uint2*)(base + fAoff + i * 8)          = hh;   // Ah
            *(uint2*)(base + TILE_B + fAoff + i * 8) = ll;   // Al
        }
        *(uint4*)(base + 2 * TILE_B + fAoff)      = *(const uint4*)bh_src;
        *(uint4*)(base + 2 * TILE_B + fAoff + 16) = *(const uint4*)(bh_src + 8);
        *(uint4*)(base + 3 * TILE_B + fAoff)      = *(const uint4*)bl_src;
        *(uint4*)(base + 3 * TILE_B + fAoff + 16) = *(const uint4*)(bl_src + 8);
    }
    __syncthreads();

    for (int c = 0; c < NCHUNK; c++) {
        const int buf = c & 1;
        const uint32_t sb = dyn + buf * BUF_B;

        // ---- stage next chunk's globals into registers (hide latency) ----
        float4 nA[4];
        uint4 nBh[2], nBl[2];
        const bool pf = (c + 1 < NCHUNK);
        if (pf) {
            const int k0 = (c + 1) * KC;
            #pragma unroll
            for (int i = 0; i < 4; i++)
                nA[i] = __ldg((const float4*)(asrc + k0 + i * 4));
            nBh[0] = *(const uint4*)(bh_src + k0);
            nBh[1] = *(const uint4*)(bh_src + k0 + 8);
            nBl[0] = *(const uint4*)(bl_src + k0);
            nBl[1] = *(const uint4*)(bl_src + k0 + 8);
        }

        // ---- compute on current buffer ----
        const uint32_t sAh = sb, sAl = sb + TILE_B;
        const uint32_t sBh = sb + 2 * TILE_B, sBl = sb + 3 * TILE_B;

        #pragma unroll
        for (int s = 0; s < 2; s++) {
            uint32_t ah[2][4], al[2][4], bb[16];
            // A fragments (row = m, col = k)
            #pragma unroll
            for (int mi = 0; mi < 2; mi++) {
                const int arow = warp_m * 32 + mi * 16 + (lg & 1) * 8 + lr;
                const int acol = s * 16 + (lg >> 1) * 8;
                const uint32_t off = arow * (PITCH * 2) + acol * 2;
                ldsm_x4(ah[mi], sAh + off);
                ldsm_x4(al[mi], sAl + off);
            }
            // Bh fragments: jp pairs of n8 tiles
            #pragma unroll
            for (int jp = 0; jp < 4; jp++) {
                const int nrow = warp_n * 64 + jp * 16 + (lg >> 1) * 8 + lr;
                const int ncol = s * 16 + (lg & 1) * 8;
                ldsm_x4(&bb[jp * 4], sBh + nrow * (PITCH * 2) + ncol * 2);
            }
            // pass 1: Ah*Bh, pass 2: Al*Bh
            #pragma unroll
            for (int mi = 0; mi < 2; mi++)
                #pragma unroll
                for (int j = 0; j < 8; j++) {
                    const uint32_t* bp = &bb[(j >> 1) * 4 + (j & 1) * 2];
                    mma_bf16(acc[mi][j], ah[mi], bp);
                }
            #pragma unroll
            for (int mi = 0; mi < 2; mi++)
                #pragma unroll
                for (int j = 0; j < 8; j++) {
                    const uint32_t* bp = &bb[(j >> 1) * 4 + (j & 1) * 2];
                    mma_bf16(acc[mi][j], al[mi], bp);
                }
            // Bl fragments, pass 3: Ah*Bl
            #pragma unroll
            for (int jp = 0; jp < 4; jp++) {
                const int nrow = warp_n * 64 + jp * 16 + (lg >> 1) * 8 + lr;
                const int ncol = s * 16 + (lg & 1) * 8;
                ldsm_x4(&bb[jp * 4], sBl + nrow * (PITCH * 2) + ncol * 2);
            }
            #pragma unroll
            for (int mi = 0; mi < 2; mi++)
                #pragma unroll
                for (int j = 0; j < 8; j++) {
                    const uint32_t* bp = &bb[(j >> 1) * 4 + (j & 1) * 2];
                    mma_bf16(acc[mi][j], ah[mi], bp);
                }
        }

        // ---- convert + store next chunk ----
        if (pf) {
            char* nb = dsm + ((c + 1) & 1) * BUF_B;
            #pragma unroll
            for (int i = 0; i < 4; i++) {
                uint2 hh, ll;
                split2(nA[i].x, nA[i].y, hh.x, ll.x);
                split2(nA[i].z, nA[i].w, hh.y, ll.y);
                *(uint2*)(nb + fAoff + i * 8)          = hh;
                *(uint2*)(nb + TILE_B + fAoff + i * 8) = ll;
            }
            *(uint4*)(nb + 2 * TILE_B + fAoff)      = nBh[0];
            *(uint4*)(nb + 2 * TILE_B + fAoff + 16) = nBh[1];
            *(uint4*)(nb + 3 * TILE_B + fAoff)      = nBl[0];
            *(uint4*)(nb + 3 * TILE_B + fAoff + 16) = nBl[1];
        }
        __syncthreads();
    }

    // ---- epilogue: bias + store to g_emb ----
    const int cbase = warp_n * 64 + (lane & 3) * 2;
    float2 bias[8];
    #pragma unroll
    for (int j = 0; j < 8; j++)
        bias[j] = *(const float2*)&b_state[cbase + j * 8];

    #pragma unroll
    for (int mi = 0; mi < 2; mi++) {
        const size_t r0 = rowBase + warp_m * 32 + mi * 16 + (lane >> 2);
        #pragma unroll
        for (int j = 0; j < 8; j++) {
            const int col = cbase + j * 8;
            float2 lo = make_float2(acc[mi][j][0] + bias[j].x,
                                    acc[mi][j][1] + bias[j].y);
            float2 hi = make_float2(acc[mi][j][2] + bias[j].x,
                                    acc[mi][j][3] + bias[j].y);
            *(float2*)&g_emb[r0 * EDIM + col]       = lo;
            *(float2*)&g_emb[(r0 + 8) * EDIM + col] = hi;
        }
    }
}

// ---------------------------------------------------------------------------
// epilogue (unchanged from passing R6 version)
// ---------------------------------------------------------------------------
__global__ void __launch_bounds__(256) epilogue_kernel(
    const int* __restrict__ action,
    const float* __restrict__ W_out,
    const float* __restrict__ b_out,
    float* __restrict__ out)
{
    __shared__ float Ws1[EDIM * ODIM];
    __shared__ float xs[8][4][EDIM];

    const int tid = threadIdx.x;
    #pragma unroll
    for (int i = 0; i < 8; i++) {
        const int idx4 = tid + i * 256;
        *(float4*)&Ws1[idx4 * 4] = *(const float4*)&W_out[idx4 * 4];
    }
    __syncthreads();

    const int w = tid >> 5;
    const int lane = tid & 31;
    const int base = blockIdx.x * 32 + w * 4;

    int acts[4];
    float wgt[4];
    #pragma unroll
    for (int i = 0; i < 4; i++) {
        acts[i] = action[(base + i) * ADIM + lane];
        float s = g_s_table[acts[i]];
        float m = s;
        #pragma unroll
        for (int o = 16; o > 0; o >>= 1)
            m = fmaxf(m, __shfl_xor_sync(0xffffffffu, m, o));
        float p = __expf(s - m);
        float sum = p;
        #pragma unroll
        for (int o = 16; o > 0; o >>= 1)
            sum += __shfl_xor_sync(0xffffffffu, sum, o);
        wgt[i] = p / sum;
    }

    float att0[4] = {0.f, 0.f, 0.f, 0.f};
    float att1[4] = {0.f, 0.f, 0.f, 0.f};
    for (int a = 0; a < 32; a++) {
        #pragma unroll
        for (int i = 0; i < 4; i++) {
            int id   = __shfl_sync(0xffffffffu, acts[i], a);
            float wa = __shfl_sync(0xffffffffu, wgt[i], a);
            float2 t2 = *(const float2*)&g_T2[id * ODIM + 2 * lane];
            att0[i] = fmaf(wa, t2.x, att0[i]);
            att1[i] = fmaf(wa, t2.y, att1[i]);
        }
    }

    #pragma unroll
    for (int i = 0; i < 4; i++) {
        float4 v = *(const float4*)&g_emb[(size_t)(base + i) * EDIM + lane * 4];
        *(float4*)&xs[w][i][lane * 4] = v;
    }
    __syncwarp();

    float acc0[4] = {0.f, 0.f, 0.f, 0.f};
    float acc1[4] = {0.f, 0.f, 0.f, 0.f};
    #pragma unroll 4
    for (int e = 0; e < EDIM; e++) {
        float2 wv = *(const float2*)&Ws1[e * ODIM + 2 * lane];
        #pragma unroll
        for (int i = 0; i < 4; i++) {
            float x = xs[w][i][e];
            acc0[i] = fmaf(x, wv.x, acc0[i]);
            acc1[i] = fmaf(x, wv.y, acc1[i]);
        }
    }

    const float2 bo = *(const float2*)&b_out[2 * lane];
    #pragma unroll
    for (int i = 0; i < 4; i++) {
        float2 r;
        r.x = acc0[i] + att0[i] + bo.x;
        r.y = acc1[i] + att1[i] + bo.y;
        *(float2*)&out[(size_t)(base + i) * ODIM + 2 * lane] = r;
    }
}

// ---------------------------------------------------------------------------
extern "C" void kernel_launch(void* const* d_in, const int* in_sizes, int n_in,
                              void* d_out, int out_size)
{
    const float* state   = (const float*)d_in[0];
    const int*   action  = (const int*)  d_in[1];
    const float* W_state = (const float*)d_in[2];
    const float* b_state = (const float*)d_in[3];
    const float* table   = (const float*)d_in[4];
    const float* W_att   = (const float*)d_in[5];
    const float* b_att   = (const float*)d_in[6];
    const float* W_out   = (const float*)d_in[7];
    const float* b_out   = (const float*)d_in[8];
    float* out = (float*)d_out;

    cudaFuncSetAttribute(gemm_mma_kernel,
                         cudaFuncAttributeMaxDynamicSharedMemorySize, DSMEM);

    prep_w_kernel<<<256, 256>>>(W_state);
    prep2_kernel<<<(NACT + 15) / 16, 256>>>(table, W_att, b_att, W_out);
    gemm_mma_kernel<<<NB / 128, 256, DSMEM>>>(state, b_state);
    epilogue_kernel<<<NB / 32, 256>>>(action, W_out, b_out, out);
}

// round 11
// speedup vs baseline: 3.1851x; 1.1252x over previous
#include <cuda_runtime.h>
#include <cuda_bf16.h>
#include <cstdint>

#define NB      16384
#define ADIM    32
#define KTOT    2048
#define EDIM    128
#define NACT    1000
#define ODIM    64

#define KC      32                 // K per chunk (bf16 elems)
#define NCHUNK  (KTOT / KC)        // 64
#define PITCH   40                 // bf16 per smem row (80B) -> conflict-free ldmatrix
#define TILE_A  (128 * PITCH * 2)  // 10240 B
#define TILE_BT (64  * PITCH * 2)  // 5120 B
#define BUF_B   (2 * TILE_A + 2 * TILE_BT)   // Ah Al Bh Bl = 30720
#define DSMEM   (2 * BUF_B)        // 61440

// ---------------- scratch ----------------
__device__ float g_s_table[NACT];
__device__ float g_T2[NACT * ODIM];
__device__ float g_bias[ODIM];
__device__ __nv_bfloat16 g_Wt_h[ODIM * KTOT];   // Wfused^T hi, [o][k]
__device__ __nv_bfloat16 g_Wt_l[ODIM * KTOT];   // Wfused^T lo

// ---------------- helpers ----------------
__device__ __forceinline__ uint32_t smem_u32(const void* p) {
    uint32_t a;
    asm("{ .reg .u64 t; cvta.to.shared.u64 t, %1; cvt.u32.u64 %0, t; }"
        : "=r"(a) : "l"(p));
    return a;
}
__device__ __forceinline__ void ldsm_x4(uint32_t* r, uint32_t addr) {
    asm volatile("ldmatrix.sync.aligned.m8n8.x4.shared.b16 {%0,%1,%2,%3}, [%4];"
                 : "=r"(r[0]), "=r"(r[1]), "=r"(r[2]), "=r"(r[3]) : "r"(addr));
}
__device__ __forceinline__ void mma_bf16(float* c, const uint32_t* a, const uint32_t* b) {
    asm volatile(
        "mma.sync.aligned.m16n8k16.row.col.f32.bf16.bf16.f32 "
        "{%0,%1,%2,%3}, {%4,%5,%6,%7}, {%8,%9}, {%0,%1,%2,%3};"
        : "+f"(c[0]), "+f"(c[1]), "+f"(c[2]), "+f"(c[3])
        : "r"(a[0]), "r"(a[1]), "r"(a[2]), "r"(a[3]), "r"(b[0]), "r"(b[1]));
}
__device__ __forceinline__ void split2(float x, float y, uint32_t& hi, uint32_t& lo) {
    __nv_bfloat162 h = __floats2bfloat162_rn(x, y);
    __nv_bfloat162 l = __floats2bfloat162_rn(x - __low2float(h), y - __high2float(h));
    hi = *reinterpret_cast<uint32_t*>(&h);
    lo = *reinterpret_cast<uint32_t*>(&l);
}

// ---------------------------------------------------------------------------
// prep_w: Wfused = W_state[2048,128] @ W_out[0:128, 0:64]  (fp32),
//         stored transposed+split bf16 -> g_Wt_h/l [64][2048].
//         g_bias[o] = b_out[o] + b_state . W1[:,o]
// grid 64 x 256: block handles 32 k-rows.
// ---------------------------------------------------------------------------
__global__ void __launch_bounds__(256) prep_w_kernel(
    const float* __restrict__ W_state, const float* __restrict__ W_out,
    const float* __restrict__ b_state, const float* __restrict__ b_out)
{
    __shared__ float W1s[EDIM * ODIM];   // 32 KB
    __shared__ float Ast[32][EDIM];      // 16 KB

    const int tid = threadIdx.x;
    const int k0 = blockIdx.x * 32;

    #pragma unroll
    for (int i = 0; i < 32; i++)
        W1s[tid + i * 256] = W_out[tid + i * 256];    // rows 0..127 of W_out
    for (int idx = tid; idx < 32 * EDIM; idx += 256) {
        const int r = idx >> 7, e = idx & 127;
        Ast[r][e] = W_state[(size_t)(k0 + r) * EDIM + e];
    }
    __syncthreads();

    const int o  = tid & 63;
    const int kk = tid >> 6;          // 0..3, 8 k each
    float acc[8];
    #pragma unroll
    for (int i = 0; i < 8; i++) {
        const int k = kk * 8 + i;
        float s = 0.f;
        #pragma unroll 8
        for (int e = 0; e < EDIM; e++)
            s = fmaf(Ast[k][e], W1s[e * ODIM + o], s);
        acc[i] = s;
    }
    uint4 hh, ll;
    split2(acc[0], acc[1], hh.x, ll.x);
    split2(acc[2], acc[3], hh.y, ll.y);
    split2(acc[4], acc[5], hh.z, ll.z);
    split2(acc[6], acc[7], hh.w, ll.w);
    const size_t base = (size_t)o * KTOT + k0 + kk * 8;
    *(uint4*)&g_Wt_h[base] = hh;
    *(uint4*)&g_Wt_l[base] = ll;

    if (blockIdx.x == 0 && tid < ODIM) {
        float b = b_out[tid];
        #pragma unroll 8
        for (int e = 0; e < EDIM; e++)
            b = fmaf(b_state[e], W1s[e * ODIM + tid], b);
        g_bias[tid] = b;
    }
}

// ---------------------------------------------------------------------------
// prep2: s_table + T2 (unchanged from R10). grid 63 x 256.
// ---------------------------------------------------------------------------
__global__ void __launch_bounds__(256) prep2_kernel(
    const float* __restrict__ table, const float* __restrict__ W_att,
    const float* __restrict__ b_att, const float* __restrict__ W_out)
{
    __shared__ float Wo2[EDIM * ODIM];
    __shared__ float rows[16][EDIM];
    __shared__ float watt[EDIM];

    const int tid = threadIdx.x;
    #pragma unroll
    for (int i = 0; i < 32; i++)
        Wo2[tid + i * 256] = W_out[EDIM * ODIM + tid + i * 256];
    if (tid < EDIM) watt[tid] = W_att[tid];

    const int r0 = blockIdx.x * 16;
    for (int idx = tid; idx < 16 * EDIM; idx += 256) {
        const int r = idx >> 7, e = idx & 127;
        rows[r][e] = (r0 + r < NACT) ? table[(size_t)(r0 + r) * EDIM + e] : 0.f;
    }
    __syncthreads();

    if (tid < 16 && r0 + tid < NACT) {
        float s = 0.f;
        #pragma unroll 8
        for (int e = 0; e < EDIM; e++) s = fmaf(rows[tid][e], watt[e], s);
        g_s_table[r0 + tid] = s + b_att[0];
    }

    #pragma unroll
    for (int i = 0; i < 4; i++) {
        const int idx = tid + i * 256;
        const int r = idx >> 6, o = idx & 63;
        if (r0 + r < NACT) {
            float acc = 0.f;
            #pragma unroll 8
            for (int e = 0; e < EDIM; e++)
                acc = fmaf(rows[r][e], Wo2[e * ODIM + o], acc);
            g_T2[(size_t)(r0 + r) * ODIM + o] = acc;
        }
    }
}

// ---------------------------------------------------------------------------
// gemm_mma: out = state @ Wfused + g_bias, bf16 3-split via mma.sync.
// CTA 128x64, 8 warps (4m x 2n, warp = 32x32), KC=32 double-buffered.
// ---------------------------------------------------------------------------
__global__ void __launch_bounds__(256)
gemm_mma_kernel(const float* __restrict__ state, float* __restrict__ out)
{
    extern __shared__ __align__(128) char dsm[];
    const uint32_t dyn = smem_u32(dsm);

    const int tid = threadIdx.x;
    const int wid = tid >> 5, lane = tid & 31;
    const int warp_m = wid & 3;          // 32 rows each
    const int warp_n = wid >> 2;         // 32 cols each
    const int rowBase = blockIdx.x * 128;

    // A fill: 2 threads per row
    const int frow = tid >> 1;           // 0..127
    const int fseg = (tid & 1) * 16;     // 0 or 16
    const float* asrc = state + (size_t)(rowBase + frow) * KTOT + fseg;
    const uint32_t fAoff = frow * (PITCH * 2) + fseg * 2;

    // B fill: 4 threads per row (64 rows), 8 k each
    const int brow = tid >> 2;           // 0..63
    const int bseg = (tid & 3) * 8;      // 0,8,16,24
    const __nv_bfloat16* bh_src = g_Wt_h + (size_t)brow * KTOT + bseg;
    const __nv_bfloat16* bl_src = g_Wt_l + (size_t)brow * KTOT + bseg;
    const uint32_t fBoff = brow * (PITCH * 2) + bseg * 2;

    const int lg = lane >> 3, lr = lane & 7;

    float acc[2][4][4];
    #pragma unroll
    for (int mi = 0; mi < 2; mi++)
        #pragma unroll
        for (int j = 0; j < 4; j++)
            #pragma unroll
            for (int q = 0; q < 4; q++) acc[mi][j][q] = 0.f;

    // ---- prologue: fill buffer 0 ----
    {
        char* base = dsm;
        #pragma unroll
        for (int i = 0; i < 4; i++) {
            float4 v = __ldg((const float4*)(asrc + i * 4));
            uint2 hh, ll;
            split2(v.x, v.y, hh.x, ll.x);
            split2(v.z, v.w, hh.y, ll.y);
            *(uint2*)(base + fAoff + i * 8)          = hh;
            *(uint2*)(base + TILE_A + fAoff + i * 8) = ll;
        }
        *(uint4*)(base + 2 * TILE_A + fBoff)           = *(const uint4*)bh_src;
        *(uint4*)(base + 2 * TILE_A + TILE_BT + fBoff) = *(const uint4*)bl_src;
    }
    __syncthreads();

    for (int c = 0; c < NCHUNK; c++) {
        const int buf = c & 1;
        const uint32_t sb = dyn + buf * BUF_B;

        float4 nA[4];
        uint4 nBh, nBl;
        const bool pf = (c + 1 < NCHUNK);
        if (pf) {
            const int k0 = (c + 1) * KC;
            #pragma unroll
            for (int i = 0; i < 4; i++)
                nA[i] = __ldg((const float4*)(asrc + k0 + i * 4));
            nBh = *(const uint4*)(bh_src + k0);
            nBl = *(const uint4*)(bl_src + k0);
        }

        const uint32_t sAh = sb, sAl = sb + TILE_A;
        const uint32_t sBh = sb + 2 * TILE_A, sBl = sb + 2 * TILE_A + TILE_BT;

        #pragma unroll
        for (int s = 0; s < 2; s++) {
            uint32_t ah[2][4], al[2][4], bb[8];
            #pragma unroll
            for (int mi = 0; mi < 2; mi++) {
                const int arow = warp_m * 32 + mi * 16 + (lg & 1) * 8 + lr;
                const int acol = s * 16 + (lg >> 1) * 8;
                const uint32_t off = arow * (PITCH * 2) + acol * 2;
                ldsm_x4(ah[mi], sAh + off);
                ldsm_x4(al[mi], sAl + off);
            }
            #pragma unroll
            for (int jp = 0; jp < 2; jp++) {
                const int nrow = warp_n * 32 + jp * 16 + (lg >> 1) * 8 + lr;
                const int ncol = s * 16 + (lg & 1) * 8;
                ldsm_x4(&bb[jp * 4], sBh + nrow * (PITCH * 2) + ncol * 2);
            }
            #pragma unroll
            for (int mi = 0; mi < 2; mi++)
                #pragma unroll
                for (int j = 0; j < 4; j++)
                    mma_bf16(acc[mi][j], ah[mi], &bb[(j >> 1) * 4 + (j & 1) * 2]);
            #pragma unroll
            for (int mi = 0; mi < 2; mi++)
                #pragma unroll
                for (int j = 0; j < 4; j++)
                    mma_bf16(acc[mi][j], al[mi], &bb[(j >> 1) * 4 + (j & 1) * 2]);
            #pragma unroll
            for (int jp = 0; jp < 2; jp++) {
                const int nrow = warp_n * 32 + jp * 16 + (lg >> 1) * 8 + lr;
                const int ncol = s * 16 + (lg & 1) * 8;
                ldsm_x4(&bb[jp * 4], sBl + nrow * (PITCH * 2) + ncol * 2);
            }
            #pragma unroll
            for (int mi = 0; mi < 2; mi++)
                #pragma unroll
                for (int j = 0; j < 4; j++)
                    mma_bf16(acc[mi][j], ah[mi], &bb[(j >> 1) * 4 + (j & 1) * 2]);
        }

        if (pf) {
            char* nb = dsm + ((c + 1) & 1) * BUF_B;
            #pragma unroll
            for (int i = 0; i < 4; i++) {
                uint2 hh, ll;
                split2(nA[i].x, nA[i].y, hh.x, ll.x);
                split2(nA[i].z, nA[i].w, hh.y, ll.y);
                *(uint2*)(nb + fAoff + i * 8)          = hh;
                *(uint2*)(nb + TILE_A + fAoff + i * 8) = ll;
            }
            *(uint4*)(nb + 2 * TILE_A + fBoff)           = nBh;
            *(uint4*)(nb + 2 * TILE_A + TILE_BT + fBoff) = nBl;
        }
        __syncthreads();
    }

    // ---- bias + store (direct to out) ----
    const int cbase = warp_n * 32 + (lane & 3) * 2;
    float2 bias[4];
    #pragma unroll
    for (int j = 0; j < 4; j++)
        bias[j] = *(const float2*)&g_bias[cbase + j * 8];

    #pragma unroll
    for (int mi = 0; mi < 2; mi++) {
        const size_t r0 = rowBase + warp_m * 32 + mi * 16 + (lane >> 2);
        #pragma unroll
        for (int j = 0; j < 4; j++) {
            const int col = cbase + j * 8;
            float2 lo = make_float2(acc[mi][j][0] + bias[j].x,
                                    acc[mi][j][1] + bias[j].y);
            float2 hi = make_float2(acc[mi][j][2] + bias[j].x,
                                    acc[mi][j][3] + bias[j].y);
            *(float2*)&out[r0 * ODIM + col]       = lo;
            *(float2*)&out[(r0 + 8) * ODIM + col] = hi;
        }
    }
}

// ---------------------------------------------------------------------------
// att_add: out[b,:] += sum_a softmax(s_table[act])_a * T2[act_a,:]
// warp per 4 rows; 8 warps/block; 512 blocks. No smem matmul anymore.
// ---------------------------------------------------------------------------
__global__ void __launch_bounds__(256) att_add_kernel(
    const int* __restrict__ action, float* __restrict__ out)
{
    const int tid = threadIdx.x;
    const int w = tid >> 5;
    const int lane = tid & 31;
    const int base = blockIdx.x * 32 + w * 4;

    int acts[4];
    float wgt[4];
    #pragma unroll
    for (int i = 0; i < 4; i++) {
        acts[i] = action[(base + i) * ADIM + lane];
        float s = g_s_table[acts[i]];
        float m = s;
        #pragma unroll
        for (int o = 16; o > 0; o >>= 1)
            m = fmaxf(m, __shfl_xor_sync(0xffffffffu, m, o));
        float p = __expf(s - m);
        float sum = p;
        #pragma unroll
        for (int o = 16; o > 0; o >>= 1)
            sum += __shfl_xor_sync(0xffffffffu, sum, o);
        wgt[i] = p / sum;
    }

    float att0[4] = {0.f, 0.f, 0.f, 0.f};
    float att1[4] = {0.f, 0.f, 0.f, 0.f};
    for (int a = 0; a < 32; a++) {
        #pragma unroll
        for (int i = 0; i < 4; i++) {
            int id   = __shfl_sync(0xffffffffu, acts[i], a);
            float wa = __shfl_sync(0xffffffffu, wgt[i], a);
            float2 t2 = *(const float2*)&g_T2[id * ODIM + 2 * lane];
            att0[i] = fmaf(wa, t2.x, att0[i]);
            att1[i] = fmaf(wa, t2.y, att1[i]);
        }
    }

    #pragma unroll
    for (int i = 0; i < 4; i++) {
        float2 v = *(float2*)&out[(size_t)(base + i) * ODIM + 2 * lane];
        v.x += att0[i];
        v.y += att1[i];
        *(float2*)&out[(size_t)(base + i) * ODIM + 2 * lane] = v;
    }
}

// ---------------------------------------------------------------------------
extern "C" void kernel_launch(void* const* d_in, const int* in_sizes, int n_in,
                              void* d_out, int out_size)
{
    const float* state   = (const float*)d_in[0];
    const int*   action  = (const int*)  d_in[1];
    const float* W_state = (const float*)d_in[2];
    const float* b_state = (const float*)d_in[3];
    const float* table   = (const float*)d_in[4];
    const float* W_att   = (const float*)d_in[5];
    const float* b_att   = (const float*)d_in[6];
    const float* W_out   = (const float*)d_in[7];
    const float* b_out   = (const float*)d_in[8];
    float* out = (float*)d_out;

    cudaFuncSetAttribute(gemm_mma_kernel,
                         cudaFuncAttributeMaxDynamicSharedMemorySize, DSMEM);

    prep_w_kernel<<<KTOT / 32, 256>>>(W_state, W_out, b_state, b_out);
    prep2_kernel<<<(NACT + 15) / 16, 256>>>(table, W_att, b_att, W_out);
    gemm_mma_kernel<<<NB / 128, 256, DSMEM>>>(state, out);
    att_add_kernel<<<NB / 32, 256>>>(action, out);
}

// round 12
// speedup vs baseline: 3.7642x; 1.1818x over previous
#include <cuda_runtime.h>
#include <cuda_bf16.h>
#include <cstdint>

#define NB      16384
#define ADIM    32
#define KTOT    2048
#define EDIM    128
#define NACT    1000
#define ODIM    64

#define KC      32                 // K per chunk (bf16 elems)
#define NCHUNK  (KTOT / KC)        // 64
#define PITCH   40                 // bf16 per smem row (80B) -> conflict-free ldmatrix
#define TILE_T  (64 * PITCH * 2)   // 5120 B per 64-row tile
#define BUF_B   (4 * TILE_T)       // Ah Al Bh Bl = 20480
#define DSMEM   (2 * BUF_B)        // 40960 (double buffer)

// ---------------- scratch ----------------
__device__ float g_s_table[NACT];
__device__ float g_T2[NACT * ODIM];
__device__ float g_bias[ODIM];
__device__ __nv_bfloat16 g_Wt_h[ODIM * KTOT];   // Wfused^T hi, [o][k]
__device__ __nv_bfloat16 g_Wt_l[ODIM * KTOT];   // Wfused^T lo

// ---------------- helpers ----------------
__device__ __forceinline__ uint32_t smem_u32(const void* p) {
    uint32_t a;
    asm("{ .reg .u64 t; cvta.to.shared.u64 t, %1; cvt.u32.u64 %0, t; }"
        : "=r"(a) : "l"(p));
    return a;
}
__device__ __forceinline__ void ldsm_x4(uint32_t* r, uint32_t addr) {
    asm volatile("ldmatrix.sync.aligned.m8n8.x4.shared.b16 {%0,%1,%2,%3}, [%4];"
                 : "=r"(r[0]), "=r"(r[1]), "=r"(r[2]), "=r"(r[3]) : "r"(addr));
}
__device__ __forceinline__ void mma_bf16(float* c, const uint32_t* a, const uint32_t* b) {
    asm volatile(
        "mma.sync.aligned.m16n8k16.row.col.f32.bf16.bf16.f32 "
        "{%0,%1,%2,%3}, {%4,%5,%6,%7}, {%8,%9}, {%0,%1,%2,%3};"
        : "+f"(c[0]), "+f"(c[1]), "+f"(c[2]), "+f"(c[3])
        : "r"(a[0]), "r"(a[1]), "r"(a[2]), "r"(a[3]), "r"(b[0]), "r"(b[1]));
}
__device__ __forceinline__ void split2(float x, float y, uint32_t& hi, uint32_t& lo) {
    __nv_bfloat162 h = __floats2bfloat162_rn(x, y);
    __nv_bfloat162 l = __floats2bfloat162_rn(x - __low2float(h), y - __high2float(h));
    hi = *reinterpret_cast<uint32_t*>(&h);
    lo = *reinterpret_cast<uint32_t*>(&l);
}

// ---------------------------------------------------------------------------
// prep_w: Wfused = W_state[2048,128] @ W_out[0:128, 0:64] (fp32),
//         stored transposed+split bf16 -> g_Wt_h/l [64][2048].
//         g_bias[o] = b_out[o] + b_state . W1[:,o]
// grid 128 x 256: block handles 16 k-rows.
// ---------------------------------------------------------------------------
__global__ void __launch_bounds__(256) prep_w_kernel(
    const float* __restrict__ W_state, const float* __restrict__ W_out,
    const float* __restrict__ b_state, const float* __restrict__ b_out)
{
    __shared__ float W1s[EDIM * ODIM];   // 32 KB
    __shared__ float Ast[16][EDIM];      // 8 KB

    const int tid = threadIdx.x;
    const int k0 = blockIdx.x * 16;

    #pragma unroll
    for (int i = 0; i < 32; i++)
        W1s[tid + i * 256] = W_out[tid + i * 256];    // rows 0..127 of W_out
    for (int idx = tid; idx < 16 * EDIM; idx += 256) {
        const int r = idx >> 7, e = idx & 127;
        Ast[r][e] = W_state[(size_t)(k0 + r) * EDIM + e];
    }
    __syncthreads();

    const int o  = tid & 63;
    const int kk = tid >> 6;          // 0..3, 4 k each
    float acc[4];
    #pragma unroll
    for (int i = 0; i < 4; i++) {
        const int k = kk * 4 + i;
        float s = 0.f;
        #pragma unroll 8
        for (int e = 0; e < EDIM; e++)
            s = fmaf(Ast[k][e], W1s[e * ODIM + o], s);
        acc[i] = s;
    }
    uint2 hh, ll;
    split2(acc[0], acc[1], hh.x, ll.x);
    split2(acc[2], acc[3], hh.y, ll.y);
    const size_t base = (size_t)o * KTOT + k0 + kk * 4;
    *(uint2*)&g_Wt_h[base] = hh;
    *(uint2*)&g_Wt_l[base] = ll;

    if (blockIdx.x == 0 && tid < ODIM) {
        float b = b_out[tid];
        #pragma unroll 8
        for (int e = 0; e < EDIM; e++)
            b = fmaf(b_state[e], W1s[e * ODIM + tid], b);
        g_bias[tid] = b;
    }
}

// ---------------------------------------------------------------------------
// prep2: s_table + T2. grid 63 x 256.
// ---------------------------------------------------------------------------
__global__ void __launch_bounds__(256) prep2_kernel(
    const float* __restrict__ table, const float* __restrict__ W_att,
    const float* __restrict__ b_att, const float* __restrict__ W_out)
{
    __shared__ float Wo2[EDIM * ODIM];
    __shared__ float rows[16][EDIM];
    __shared__ float watt[EDIM];

    const int tid = threadIdx.x;
    #pragma unroll
    for (int i = 0; i < 32; i++)
        Wo2[tid + i * 256] = W_out[EDIM * ODIM + tid + i * 256];
    if (tid < EDIM) watt[tid] = W_att[tid];

    const int r0 = blockIdx.x * 16;
    for (int idx = tid; idx < 16 * EDIM; idx += 256) {
        const int r = idx >> 7, e = idx & 127;
        rows[r][e] = (r0 + r < NACT) ? table[(size_t)(r0 + r) * EDIM + e] : 0.f;
    }
    __syncthreads();

    if (tid < 16 && r0 + tid < NACT) {
        float s = 0.f;
        #pragma unroll 8
        for (int e = 0; e < EDIM; e++) s = fmaf(rows[tid][e], watt[e], s);
        g_s_table[r0 + tid] = s + b_att[0];
    }

    #pragma unroll
    for (int i = 0; i < 4; i++) {
        const int idx = tid + i * 256;
        const int r = idx >> 6, o = idx & 63;
        if (r0 + r < NACT) {
            float acc = 0.f;
            #pragma unroll 8
            for (int e = 0; e < EDIM; e++)
                acc = fmaf(rows[r][e], Wo2[e * ODIM + o], acc);
            g_T2[(size_t)(r0 + r) * ODIM + o] = acc;
        }
    }
}

// ---------------------------------------------------------------------------
// gemm_mma: out = state @ Wfused + g_bias, bf16 3-split via mma.sync.
// CTA 64x64, 8 warps (2m x 4n, warp = 32x16), KC=32 double-buffered.
// grid 256 -> 2 CTAs/SM for latency hiding.
// ---------------------------------------------------------------------------
__global__ void __launch_bounds__(256, 2)
gemm_mma_kernel(const float* __restrict__ state, float* __restrict__ out)
{
    extern __shared__ __align__(128) char dsm[];
    const uint32_t dyn = smem_u32(dsm);

    const int tid = threadIdx.x;
    const int wid = tid >> 5, lane = tid & 31;
    const int warp_m = wid & 1;          // 2 groups of 32 rows
    const int warp_n = wid >> 1;         // 4 groups of 16 cols
    const int rowBase = blockIdx.x * 64;

    // fills: 4 threads per row, 8 k each
    const int frow = tid >> 2;           // 0..63
    const int fseg = (tid & 3) * 8;      // 0,8,16,24
    const float* asrc = state + (size_t)(rowBase + frow) * KTOT + fseg;
    const __nv_bfloat16* bh_src = g_Wt_h + (size_t)frow * KTOT + fseg;
    const __nv_bfloat16* bl_src = g_Wt_l + (size_t)frow * KTOT + fseg;
    const uint32_t foff = frow * (PITCH * 2) + fseg * 2;   // byte offset

    const int lg = lane >> 3, lr = lane & 7;

    float acc[2][2][4];
    #pragma unroll
    for (int mi = 0; mi < 2; mi++)
        #pragma unroll
        for (int j = 0; j < 2; j++)
            #pragma unroll
            for (int q = 0; q < 4; q++) acc[mi][j][q] = 0.f;

    // ---- prologue: fill buffer 0 ----
    {
        char* base = dsm;
        float4 v0 = __ldg((const float4*)asrc);
        float4 v1 = __ldg((const float4*)(asrc + 4));
        uint4 hh, ll;
        split2(v0.x, v0.y, hh.x, ll.x);
        split2(v0.z, v0.w, hh.y, ll.y);
        split2(v1.x, v1.y, hh.z, ll.z);
        split2(v1.z, v1.w, hh.w, ll.w);
        *(uint4*)(base + foff)              = hh;                      // Ah
        *(uint4*)(base + TILE_T + foff)     = ll;                      // Al
        *(uint4*)(base + 2 * TILE_T + foff) = *(const uint4*)bh_src;   // Bh
        *(uint4*)(base + 3 * TILE_T + foff) = *(const uint4*)bl_src;   // Bl
    }
    __syncthreads();

    for (int c = 0; c < NCHUNK; c++) {
        const int buf = c & 1;
        const uint32_t sb = dyn + buf * BUF_B;

        // stage next chunk's globals
        float4 nA0, nA1;
        uint4 nBh, nBl;
        const bool pf = (c + 1 < NCHUNK);
        if (pf) {
            const int k0 = (c + 1) * KC;
            nA0 = __ldg((const float4*)(asrc + k0));
            nA1 = __ldg((const float4*)(asrc + k0 + 4));
            nBh = *(const uint4*)(bh_src + k0);
            nBl = *(const uint4*)(bl_src + k0);
        }

        const uint32_t sAh = sb, sAl = sb + TILE_T;
        const uint32_t sBh = sb + 2 * TILE_T, sBl = sb + 3 * TILE_T;

        #pragma unroll
        for (int s = 0; s < 2; s++) {
            uint32_t ah[2][4], al[2][4], bb[4];
            #pragma unroll
            for (int mi = 0; mi < 2; mi++) {
                const int arow = warp_m * 32 + mi * 16 + (lg & 1) * 8 + lr;
                const int acol = s * 16 + (lg >> 1) * 8;
                const uint32_t off = arow * (PITCH * 2) + acol * 2;
                ldsm_x4(ah[mi], sAh + off);
                ldsm_x4(al[mi], sAl + off);
            }
            {
                const int nrow = warp_n * 16 + (lg >> 1) * 8 + lr;
                const int ncol = s * 16 + (lg & 1) * 8;
                ldsm_x4(bb, sBh + nrow * (PITCH * 2) + ncol * 2);
            }
            #pragma unroll
            for (int mi = 0; mi < 2; mi++)
                #pragma unroll
                for (int j = 0; j < 2; j++)
                    mma_bf16(acc[mi][j], ah[mi], &bb[j * 2]);
            #pragma unroll
            for (int mi = 0; mi < 2; mi++)
                #pragma unroll
                for (int j = 0; j < 2; j++)
                    mma_bf16(acc[mi][j], al[mi], &bb[j * 2]);
            {
                const int nrow = warp_n * 16 + (lg >> 1) * 8 + lr;
                const int ncol = s * 16 + (lg & 1) * 8;
                ldsm_x4(bb, sBl + nrow * (PITCH * 2) + ncol * 2);
            }
            #pragma unroll
            for (int mi = 0; mi < 2; mi++)
                #pragma unroll
                for (int j = 0; j < 2; j++)
                    mma_bf16(acc[mi][j], ah[mi], &bb[j * 2]);
        }

        if (pf) {
            char* nb = dsm + ((c + 1) & 1) * BUF_B;
            uint4 hh, ll;
            split2(nA0.x, nA0.y, hh.x, ll.x);
            split2(nA0.z, nA0.w, hh.y, ll.y);
            split2(nA1.x, nA1.y, hh.z, ll.z);
            split2(nA1.z, nA1.w, hh.w, ll.w);
            *(uint4*)(nb + foff)              = hh;
            *(uint4*)(nb + TILE_T + foff)     = ll;
            *(uint4*)(nb + 2 * TILE_T + foff) = nBh;
            *(uint4*)(nb + 3 * TILE_T + foff) = nBl;
        }
        __syncthreads();
    }

    // ---- bias + store ----
    const int cbase = warp_n * 16 + (lane & 3) * 2;
    float2 bias[2];
    #pragma unroll
    for (int j = 0; j < 2; j++)
        bias[j] = *(const float2*)&g_bias[cbase + j * 8];

    #pragma unroll
    for (int mi = 0; mi < 2; mi++) {
        const size_t r0 = rowBase + warp_m * 32 + mi * 16 + (lane >> 2);
        #pragma unroll
        for (int j = 0; j < 2; j++) {
            const int col = cbase + j * 8;
            float2 lo = make_float2(acc[mi][j][0] + bias[j].x,
                                    acc[mi][j][1] + bias[j].y);
            float2 hi = make_float2(acc[mi][j][2] + bias[j].x,
                                    acc[mi][j][3] + bias[j].y);
            *(float2*)&out[r0 * ODIM + col]       = lo;
            *(float2*)&out[(r0 + 8) * ODIM + col] = hi;
        }
    }
}

// ---------------------------------------------------------------------------
// att_add: out[b,:] += sum_a softmax(s_table[act])_a * T2[act_a,:]
// ---------------------------------------------------------------------------
__global__ void __launch_bounds__(256) att_add_kernel(
    const int* __restrict__ action, float* __restrict__ out)
{
    const int tid = threadIdx.x;
    const int w = tid >> 5;
    const int lane = tid & 31;
    const int base = blockIdx.x * 32 + w * 4;

    int acts[4];
    float wgt[4];
    #pragma unroll
    for (int i = 0; i < 4; i++) {
        acts[i] = action[(base + i) * ADIM + lane];
        float s = g_s_table[acts[i]];
        float m = s;
        #pragma unroll
        for (int o = 16; o > 0; o >>= 1)
            m = fmaxf(m, __shfl_xor_sync(0xffffffffu, m, o));
        float p = __expf(s - m);
        float sum = p;
        #pragma unroll
        for (int o = 16; o > 0; o >>= 1)
            sum += __shfl_xor_sync(0xffffffffu, sum, o);
        wgt[i] = p / sum;
    }

    float att0[4] = {0.f, 0.f, 0.f, 0.f};
    float att1[4] = {0.f, 0.f, 0.f, 0.f};
    for (int a = 0; a < 32; a++) {
        #pragma unroll
        for (int i = 0; i < 4; i++) {
            int id   = __shfl_sync(0xffffffffu, acts[i], a);
            float wa = __shfl_sync(0xffffffffu, wgt[i], a);
            float2 t2 = *(const float2*)&g_T2[id * ODIM + 2 * lane];
            att0[i] = fmaf(wa, t2.x, att0[i]);
            att1[i] = fmaf(wa, t2.y, att1[i]);
        }
    }

    #pragma unroll
    for (int i = 0; i < 4; i++) {
        float2 v = *(float2*)&out[(size_t)(base + i) * ODIM + 2 * lane];
        v.x += att0[i];
        v.y += att1[i];
        *(float2*)&out[(size_t)(base + i) * ODIM + 2 * lane] = v;
    }
}

// ---------------------------------------------------------------------------
extern "C" void kernel_launch(void* const* d_in, const int* in_sizes, int n_in,
                              void* d_out, int out_size)
{
    const float* state   = (const float*)d_in[0];
    const int*   action  = (const int*)  d_in[1];
    const float* W_state = (const float*)d_in[2];
    const float* b_state = (const float*)d_in[3];
    const float* table   = (const float*)d_in[4];
    const float* W_att   = (const float*)d_in[5];
    const float* b_att   = (const float*)d_in[6];
    const float* W_out   = (const float*)d_in[7];
    const float* b_out   = (const float*)d_in[8];
    float* out = (float*)d_out;

    cudaFuncSetAttribute(gemm_mma_kernel,
                         cudaFuncAttributeMaxDynamicSharedMemorySize, DSMEM);

    prep_w_kernel<<<KTOT / 16, 256>>>(W_state, W_out, b_state, b_out);
    prep2_kernel<<<(NACT + 15) / 16, 256>>>(table, W_att, b_att, W_out);
    gemm_mma_kernel<<<NB / 64, 256, DSMEM>>>(state, out);
    att_add_kernel<<<NB / 32, 256>>>(action, out);
}